// round 10
// baseline (speedup 1.0000x reference)
#include <cuda_runtime.h>
#include <math.h>

// ---------------------------------------------------------------------------
// RPN forward, batch -1 only.
// prep (tf32 hi/lo split of X and W) -> 3x3 conv as implicit GEMM on
// mma.sync.m16n8k8.tf32 (3xTF32) -> head GEMM + decode + histogram ->
// bucket prefix -> scatter -> exact local rank -> NMS mask (yy2=max bug) ->
// chunk-batched serial scan -> 300x4 output.
// R9 fix: B-tile smem load was copying only 4 of 8 float2 per thread.
// ---------------------------------------------------------------------------

#define FSZ   50
#define NCH   512
#define NKEYS 22500
#define PRE_NMS 6000
#define POST_NMS 300
#define NWORDS 188
#define NBUCK 65536

#define MP    2816
#define MT    21
#define BMc   128
#define BNc   64
#define BKc   32
#define APAD  34
#define BPAD  66

__device__ float2 g_Xhl[MP * NCH];                 // [p][ic] (hi,lo)
__device__ float2 g_Whl[9 * NCH * NCH];            // [tap][ic][oc] (hi,lo)
__device__ float  g_feat[FSZ * FSZ * NCH];         // [s][oc]
__device__ float4 g_boxes[NKEYS];
__device__ unsigned g_hi[NKEYS];
__device__ unsigned g_hist[NBUCK];
__device__ unsigned g_bcnt[NBUCK];
__device__ unsigned g_bstart[NBUCK + 1];
__device__ unsigned long long g_skey[NKEYS];
__device__ int    g_C;
__device__ float4 g_sboxes[PRE_NMS];
__device__ unsigned g_mask[PRE_NMS * NWORDS];

__device__ __forceinline__ float2 tf32_split(float x) {
    unsigned uh;
    asm("cvt.rna.tf32.f32 %0, %1;" : "=r"(uh) : "f"(x));
    float hi = __uint_as_float(uh);
    float r = x - hi;
    unsigned ul;
    asm("cvt.rna.tf32.f32 %0, %1;" : "=r"(ul) : "f"(r));
    return make_float2(hi, __uint_as_float(ul));
}

__device__ __forceinline__ void mma_tf32(float* d,
                                         float a0, float a1, float a2, float a3,
                                         float b0, float b1) {
    asm volatile(
        "mma.sync.aligned.m16n8k8.row.col.f32.tf32.tf32.f32 "
        "{%0,%1,%2,%3}, {%4,%5,%6,%7}, {%8,%9}, {%0,%1,%2,%3};"
        : "+f"(d[0]), "+f"(d[1]), "+f"(d[2]), "+f"(d[3])
        : "r"(__float_as_uint(a0)), "r"(__float_as_uint(a1)),
          "r"(__float_as_uint(a2)), "r"(__float_as_uint(a3)),
          "r"(__float_as_uint(b0)), "r"(__float_as_uint(b1)));
}

// ---------------------------------------------------------------------------
__global__ void prep_x(const float* __restrict__ in) {
    int idx = blockIdx.x * blockDim.x + threadIdx.x;
    if (idx >= MP * NCH) return;
    int p = idx >> 9, c = idx & 511;
    float v = 0.0f;
    if (p < 2704) {
        int y = p / 52, x = p - y * 52;
        if (y >= 1 && y <= FSZ && x >= 1 && x <= FSZ)
            v = in[((7 * NCH + c) * FSZ + (y - 1)) * FSZ + (x - 1)];
    }
    g_Xhl[idx] = tf32_split(v);
}

__global__ void prep_w(const float* __restrict__ w) {
    int idx = blockIdx.x * blockDim.x + threadIdx.x;
    if (idx < NBUCK) { g_hist[idx] = 0u; g_bcnt[idx] = 0u; }
    if (idx >= 9 * NCH * NCH) return;
    int tap = idx % 9;
    int ic  = (idx / 9) % NCH;
    int oc  = idx / (9 * NCH);
    g_Whl[(tap * NCH + ic) * NCH + oc] = tf32_split(w[idx]);
}

// ---------------------------------------------------------------------------
// Implicit-GEMM conv on tf32 tensor cores (3xTF32).
// grid = (8 oc-tiles, 21 m-tiles), 256 threads = 8 warps (4M x 2N).
// ---------------------------------------------------------------------------
__global__ void __launch_bounds__(256) conv_kernel(const float* __restrict__ bias) {
    extern __shared__ float2 sm2[];
    float2* As = sm2;                       // [BMc][APAD]
    float2* Bs = sm2 + BMc * APAD;          // [BKc][BPAD]

    const int tid = threadIdx.x;
    const int wid = tid >> 5, lid = tid & 31;
    const int gid = lid >> 2, tg = lid & 3;
    const int mw = wid >> 1, nw = wid & 1;
    const int mtile = blockIdx.y;
    const int ocb = blockIdx.x * BNc;
    const int mbase = mtile * BMc;

    float acc[2][4][4];
#pragma unroll
    for (int i = 0; i < 2; ++i)
#pragma unroll
        for (int j = 0; j < 4; ++j)
#pragma unroll
            for (int q = 0; q < 4; ++q) acc[i][j][q] = 0.0f;

    const int lm = tid >> 1, lhalf = (tid & 1) * 16;
    const int lk = tid >> 3, lseg = (tid & 7) * 8;

    for (int ch = 0; ch < 144; ++ch) {
        const int tap = ch >> 4;
        const int ic0 = (ch & 15) * BKc;
        const int kh = tap / 3, kw = tap - kh * 3;
        const int pbase = mbase + kh * 52 + kw;

        __syncthreads();
        {   // A: 16 float2 per thread (8 float4)
            const float4* src = reinterpret_cast<const float4*>(
                &g_Xhl[(pbase + lm) * NCH + ic0 + lhalf]);
            float4* dst = reinterpret_cast<float4*>(&As[lm * APAD + lhalf]);
#pragma unroll
            for (int q = 0; q < 8; ++q) dst[q] = src[q];
        }
        {   // B: 8 float2 per thread (4 float4)  [R9 FIX: was 2 float4]
            const float4* src = reinterpret_cast<const float4*>(
                &g_Whl[(tap * NCH + ic0 + lk) * NCH + ocb + lseg]);
            float4* dst = reinterpret_cast<float4*>(&Bs[lk * BPAD + lseg]);
#pragma unroll
            for (int q = 0; q < 4; ++q) dst[q] = src[q];
        }
        __syncthreads();

#pragma unroll
        for (int k8 = 0; k8 < 4; ++k8) {
            const int kb = k8 * 8;
            float2 a[2][4];
#pragma unroll
            for (int i = 0; i < 2; ++i) {
                int r0 = mw * 32 + i * 16 + gid;
                a[i][0] = As[r0 * APAD + kb + tg];
                a[i][1] = As[(r0 + 8) * APAD + kb + tg];
                a[i][2] = As[r0 * APAD + kb + tg + 4];
                a[i][3] = As[(r0 + 8) * APAD + kb + tg + 4];
            }
            float2 b[4][2];
#pragma unroll
            for (int j = 0; j < 4; ++j) {
                int nn = nw * 32 + j * 8 + gid;
                b[j][0] = Bs[(kb + tg) * BPAD + nn];
                b[j][1] = Bs[(kb + tg + 4) * BPAD + nn];
            }
#pragma unroll
            for (int i = 0; i < 2; ++i)
#pragma unroll
                for (int j = 0; j < 4; ++j) {
                    mma_tf32(acc[i][j], a[i][0].y, a[i][1].y, a[i][2].y, a[i][3].y,
                             b[j][0].x, b[j][1].x);                 // lo x hi
                    mma_tf32(acc[i][j], a[i][0].x, a[i][1].x, a[i][2].x, a[i][3].x,
                             b[j][0].y, b[j][1].y);                 // hi x lo
                    mma_tf32(acc[i][j], a[i][0].x, a[i][1].x, a[i][2].x, a[i][3].x,
                             b[j][0].x, b[j][1].x);                 // hi x hi
                }
        }
    }

#pragma unroll
    for (int i = 0; i < 2; ++i) {
#pragma unroll
        for (int j = 0; j < 4; ++j) {
            int oc = ocb + nw * 32 + j * 8 + 2 * tg;
            float bx = bias[oc], by = bias[oc + 1];
#pragma unroll
            for (int half = 0; half < 2; ++half) {
                int b = mbase + mw * 32 + i * 16 + gid + half * 8;
                int hh = b / 52, ww = b - hh * 52;
                if (hh < FSZ && ww < FSZ) {
                    float v0 = acc[i][j][half * 2 + 0] + bx;
                    float v1 = acc[i][j][half * 2 + 1] + by;
                    v0 = (v0 >= 0.0f) ? v0 : 0.01f * v0;
                    v1 = (v1 >= 0.0f) ? v1 : 0.01f * v1;
                    *reinterpret_cast<float2*>(&g_feat[(hh * FSZ + ww) * NCH + oc]) =
                        make_float2(v0, v1);
                }
            }
        }
    }
}

// ---------------------------------------------------------------------------
// Head (unchanged, proven 34.5us).
// ---------------------------------------------------------------------------
#define HB 16
#define WPAD 516
__global__ void __launch_bounds__(512) head_kernel(const float* __restrict__ rw,
                                                   const float* __restrict__ rb,
                                                   const float* __restrict__ cw,
                                                   const float* __restrict__ cb) {
    extern __shared__ float sh[];
    float* Wsp = sh;
    float* ft  = sh + 54 * WPAD;
    __shared__ float bb[54];
    __shared__ float par[2 * HB * 54];
    __shared__ float vals[HB * 54];

    const int tid = threadIdx.x;
    const int s0 = blockIdx.x * HB;

    for (int e = tid; e < 54 * NCH; e += 512) {
        int o = e >> 9, k = e & 511;
        Wsp[o * WPAD + k] = (o < 36) ? rw[o * NCH + k] : cw[(o - 36) * NCH + k];
    }
    if (tid < 54) bb[tid] = (tid < 36) ? rb[tid] : cb[tid - 36];
    for (int e = tid; e < HB * (NCH / 4); e += 512) {
        int sl = e >> 7, k4 = e & 127;
        int s = s0 + sl;
        float4 v = make_float4(0.f, 0.f, 0.f, 0.f);
        if (s < FSZ * FSZ) v = reinterpret_cast<const float4*>(g_feat + s * NCH)[k4];
        reinterpret_cast<float4*>(ft + sl * NCH)[k4] = v;
    }
    __syncthreads();

    const int o  = tid & 63;
    const int r  = tid >> 6;
    const int kh = r >> 2;
    const int sg = r & 3;
    if (o < 54) {
        const float4* w4 = reinterpret_cast<const float4*>(Wsp + o * WPAD) + kh * 64;
        const float4* f0 = reinterpret_cast<const float4*>(ft + (sg * 4 + 0) * NCH) + kh * 64;
        const float4* f1 = reinterpret_cast<const float4*>(ft + (sg * 4 + 1) * NCH) + kh * 64;
        const float4* f2 = reinterpret_cast<const float4*>(ft + (sg * 4 + 2) * NCH) + kh * 64;
        const float4* f3 = reinterpret_cast<const float4*>(ft + (sg * 4 + 3) * NCH) + kh * 64;
        float a0 = 0.f, a1 = 0.f, a2 = 0.f, a3 = 0.f;
#pragma unroll 4
        for (int c = 0; c < 64; ++c) {
            float4 w = w4[c];
            float4 f = f0[c];
            a0 += w.x * f.x; a0 += w.y * f.y; a0 += w.z * f.z; a0 += w.w * f.w;
            f = f1[c];
            a1 += w.x * f.x; a1 += w.y * f.y; a1 += w.z * f.z; a1 += w.w * f.w;
            f = f2[c];
            a2 += w.x * f.x; a2 += w.y * f.y; a2 += w.z * f.z; a2 += w.w * f.w;
            f = f3[c];
            a3 += w.x * f.x; a3 += w.y * f.y; a3 += w.z * f.z; a3 += w.w * f.w;
        }
        par[(kh * HB + sg * 4 + 0) * 54 + o] = a0;
        par[(kh * HB + sg * 4 + 1) * 54 + o] = a1;
        par[(kh * HB + sg * 4 + 2) * 54 + o] = a2;
        par[(kh * HB + sg * 4 + 3) * 54 + o] = a3;
    }
    __syncthreads();

    for (int e = tid; e < HB * 54; e += 512) {
        int oo = e % 54;
        vals[e] = (par[e] + par[HB * 54 + e]) + bb[oo];
    }
    __syncthreads();

    if (tid < HB * 9) {
        int sl = tid / 9, a = tid - sl * 9;
        int s = s0 + sl;
        if (s < FSZ * FSZ) {
            const float* v = &vals[sl * 54];
            float pr0 = v[a * 4 + 0], pr1 = v[a * 4 + 1];
            float pr2 = v[a * 4 + 2], pr3 = v[a * 4 + 3];
            float l0 = v[36 + a * 2], l1 = v[36 + a * 2 + 1];
            float m = fmaxf(l0, l1);
            float e0 = expf(l0 - m), e1 = expf(l1 - m);
            float score = e1 / (e0 + e1);

            int hh = s / FSZ, ww = s - hh * FSZ;
            float cx = (float)(16 * hh + 8);
            float cy = (float)(16 * ww + 8);
            int rr = a / 3, q = a - rr * 3;
            float basev = (q == 0) ? 128.0f : (q == 1 ? 256.0f : 512.0f);
            float sq_r  = (rr == 0) ? sqrtf(0.5f) : (rr == 1 ? 1.0f : sqrtf(2.0f));
            float sq_ir = (rr == 0) ? sqrtf(2.0f) : (rr == 1 ? 1.0f : sqrtf(0.5f));
            float hsv = basev * sq_r;
            float wsv = basev * sq_ir;
            float ax1 = cx - wsv * 0.5f;
            float ay1 = cy - hsv * 0.5f;

            float t1 = pr0 + ax1;
            float t2 = pr1 + ay1;
            float rx1 = fminf(fmaxf(t1, 0.0f), 799.0f);
            float ry1 = fminf(fmaxf(t2, 0.0f), 799.0f);
            float rx2 = fminf(fmaxf((t1 + pr2) + wsv, 0.0f), 799.0f);
            float ry2 = fminf(fmaxf((t2 + pr3) + hsv, 0.0f), 799.0f);

            float wv = pr2 + wsv, hv = pr3 + hsv;
            bool valid = (wv >= 16.0f) && (hv >= 16.0f);
            float sm = valid ? score : -INFINITY;

            unsigned u = __float_as_uint(sm);
            unsigned vm = (u & 0x80000000u) ? ~u : (u | 0x80000000u);
            unsigned hi = ~vm;
            int gi = s * 9 + a;
            g_hi[gi] = hi;
            atomicAdd(&g_hist[hi >> 16], 1u);
            g_boxes[gi] = make_float4(rx1, ry1, rx2, ry2);
        }
    }
}

// ---------------------------------------------------------------------------
__global__ void __launch_bounds__(1024) prefix_kernel() {
    const int tid = threadIdx.x;
    const int base = tid * 64;
    unsigned sum = 0;
    for (int k = 0; k < 64; ++k) sum += g_hist[base + k];

    unsigned lane = tid & 31, w = tid >> 5;
    unsigned inc = sum;
#pragma unroll
    for (int d = 1; d < 32; d <<= 1) {
        unsigned n = __shfl_up_sync(0xFFFFFFFFu, inc, d);
        if (lane >= d) inc += n;
    }
    __shared__ unsigned wsum[32];
    if (lane == 31) wsum[w] = inc;
    __syncthreads();
    if (w == 0) {
        unsigned x = wsum[lane];
#pragma unroll
        for (int d = 1; d < 32; d <<= 1) {
            unsigned n = __shfl_up_sync(0xFFFFFFFFu, x, d);
            if (lane >= d) x += n;
        }
        wsum[lane] = x;
    }
    __syncthreads();
    unsigned run = inc - sum + (w ? wsum[w - 1] : 0u);
    for (int k = 0; k < 64; ++k) {
        unsigned hcount = g_hist[base + k];
        g_bstart[base + k] = run;
        unsigned nx = run + hcount;
        if (run < PRE_NMS && nx >= PRE_NMS) g_C = (int)nx;
        run = nx;
    }
    if (tid == 1023) g_bstart[NBUCK] = run;
}

__global__ void __launch_bounds__(256) scatter_kernel() {
    int i = blockIdx.x * 256 + threadIdx.x;
    if (i >= NKEYS) return;
    unsigned hi = g_hi[i];
    unsigned b = hi >> 16;
    unsigned st = g_bstart[b];
    if (st < PRE_NMS) {
        unsigned pos = st + atomicAdd(&g_bcnt[b], 1u);
        g_skey[pos] = ((unsigned long long)hi << 15) | (unsigned)i;
    }
}

__global__ void __launch_bounds__(256) localrank_kernel() {
    int p = blockIdx.x * 256 + threadIdx.x;
    if (p >= g_C) return;
    unsigned long long key = g_skey[p];
    unsigned hi = (unsigned)(key >> 15);
    unsigned b = hi >> 16;
    int s = (int)g_bstart[b], e = (int)g_bstart[b + 1];
    int r = s;
    for (int q = s; q < e; ++q) r += (g_skey[q] < key) ? 1 : 0;
    if (r < PRE_NMS) g_sboxes[r] = g_boxes[key & 0x7FFFu];
}

// ---------------------------------------------------------------------------
__global__ void __launch_bounds__(32) mask_kernel() {
    const int bi = blockIdx.y, bj = blockIdx.x;
    if (bj < bi) return;
    const int t = threadIdx.x;
    const int i = bi * 32 + t;

    __shared__ float4 bx[32];
    __shared__ float ar[32];
    const int j0 = bj * 32;
    if (j0 + t < PRE_NMS) {
        float4 b = g_sboxes[j0 + t];
        bx[t] = b;
        ar[t] = ((b.z - b.x) + 1.0f) * ((b.w - b.y) + 1.0f);
    }
    __syncwarp();
    if (i >= PRE_NMS) return;

    float4 bi4 = g_sboxes[i];
    float areai = ((bi4.z - bi4.x) + 1.0f) * ((bi4.w - bi4.y) + 1.0f);
    unsigned word = 0;
    int jmax = min(32, PRE_NMS - j0);
    for (int jj = 0; jj < jmax; ++jj) {
        int jg = j0 + jj;
        if (jg <= i) continue;
        float4 bj4 = bx[jj];
        float xx1 = fmaxf(bi4.x, bj4.x);
        float yy1 = fmaxf(bi4.y, bj4.y);
        float xx2 = fminf(bi4.z, bj4.z);
        float yy2 = fmaxf(bi4.w, bj4.w);              // reference bug
        float w = fmaxf(0.0f, (xx2 - xx1) + 1.0f);
        float h = fmaxf(0.0f, (yy2 - yy1) + 1.0f);
        float inter = w * h;
        float ov = inter / ((areai + ar[jj]) - inter);
        if (ov > 0.7f) word |= (1u << jj);
    }
    g_mask[i * NWORDS + bj] = word;
}

// ---------------------------------------------------------------------------
__global__ void __launch_bounds__(256) scan_kernel(float* __restrict__ out) {
    __shared__ unsigned keep[NWORDS];
    __shared__ unsigned sdiag[32];
    __shared__ unsigned curAlive;
    __shared__ int pref[NWORDS + 1];
    const int tid = threadIdx.x;
    if (tid < NWORDS) keep[tid] = (tid == NWORDS - 1) ? 0x0000FFFFu : 0xFFFFFFFFu;
    __syncthreads();

    for (int c = 0; c < NWORDS; ++c) {
        if (tid < 32) {
            int i = c * 32 + tid;
            sdiag[tid] = (i < PRE_NMS) ? g_mask[i * NWORDS + c] : 0u;
            __syncwarp();
            if (tid == 0) {
                unsigned alive = keep[c];
                unsigned rem = alive;
                while (rem) {
                    int b = __ffs(rem) - 1;
                    rem &= rem - 1u;
                    alive &= ~sdiag[b];
                    rem &= alive;
                }
                keep[c] = alive;
                curAlive = alive;
            }
        }
        __syncthreads();
        unsigned alive = curAlive;
        if (alive) {
            for (int w2 = c + 1 + tid; w2 < NWORDS; w2 += 256) {
                unsigned nm = 0;
                unsigned a = alive;
                while (a) {
                    int b = __ffs(a) - 1;
                    a &= a - 1u;
                    nm |= g_mask[(c * 32 + b) * NWORDS + w2];
                }
                keep[w2] &= ~nm;
            }
        }
        __syncthreads();
    }

    if (tid == 0) {
        int run = 0;
        pref[0] = 0;
        for (int w = 0; w < NWORDS; ++w) { run += __popc(keep[w]); pref[w + 1] = run; }
    }
    __syncthreads();
    const int K = pref[NWORDS];

    for (int i = tid; i < PRE_NMS; i += 256) {
        int w = i >> 5, b = i & 31;
        unsigned kwv = keep[w];
        int kp = pref[w] + __popc(kwv & ((1u << b) - 1u));
        int pos = ((kwv >> b) & 1u) ? kp : (K + (i - kp));
        if (pos < POST_NMS) {
            float4 bb = g_sboxes[i];
            out[pos * 4 + 0] = bb.x;
            out[pos * 4 + 1] = bb.y;
            out[pos * 4 + 2] = (bb.z - bb.x) + 1.0f;
            out[pos * 4 + 3] = (bb.w - bb.y) + 1.0f;
        }
    }
}

// ---------------------------------------------------------------------------
extern "C" void kernel_launch(void* const* d_in, const int* in_sizes, int n_in,
                              void* d_out, int out_size) {
    const float* in_features = (const float*)d_in[0];
    const float* conv_w      = (const float*)d_in[1];
    const float* conv_b      = (const float*)d_in[2];
    const float* reg_w       = (const float*)d_in[3];
    const float* reg_b       = (const float*)d_in[4];
    const float* cls_w       = (const float*)d_in[5];
    const float* cls_b       = (const float*)d_in[6];
    float* out = (float*)d_out;

    const int conv_smem = (BMc * APAD + BKc * BPAD) * (int)sizeof(float2);
    cudaFuncSetAttribute(conv_kernel, cudaFuncAttributeMaxDynamicSharedMemorySize, conv_smem);
    const int head_smem = (54 * WPAD + HB * NCH) * (int)sizeof(float);
    cudaFuncSetAttribute(head_kernel, cudaFuncAttributeMaxDynamicSharedMemorySize, head_smem);

    prep_x<<<(MP * NCH + 255) / 256, 256>>>(in_features);
    prep_w<<<(9 * NCH * NCH + 255) / 256, 256>>>(conv_w);
    conv_kernel<<<dim3(8, MT), 256, conv_smem>>>(conv_b);
    head_kernel<<<(FSZ * FSZ + HB - 1) / HB, 512, head_smem>>>(reg_w, reg_b, cls_w, cls_b);
    prefix_kernel<<<1, 1024>>>();
    scatter_kernel<<<(NKEYS + 255) / 256, 256>>>();
    localrank_kernel<<<(NKEYS + 255) / 256, 256>>>();
    mask_kernel<<<dim3(NWORDS, NWORDS), 32>>>();
    scan_kernel<<<1, 256>>>(out);
}

// round 15
// speedup vs baseline: 2.1349x; 2.1349x over previous
#include <cuda_runtime.h>
#include <math.h>

// ---------------------------------------------------------------------------
// RPN forward, batch -1 only.
// Winograd F(2x2,3x3) conv: prep_x (V=B^T d B) + prep_w (U=G g G^T) ->
// 16 batched fp32 GEMMs [oc512 x ic512 x tiles625] -> output transform
// (Y=A^T M A + bias + leaky) -> head GEMM + decode + histogram -> bucket
// prefix -> scatter -> exact local rank -> NMS mask (yy2=max bug) ->
// chunk-batched serial scan -> 300x4 output.  (fp32 everywhere; tensor
// path is unavailable: harness compiles virtual arch compute_103, no 'a'.)
// ---------------------------------------------------------------------------

#define FSZ   50
#define NCH   512
#define NKEYS 22500
#define PRE_NMS 6000
#define POST_NMS 300
#define NWORDS 188
#define NBUCK 65536

#define NTIL  625              // 25x25 winograd tiles
#define NTP   640              // padded tile count

__device__ float g_V[16 * NCH * NTP];              // [xi][ic][tile]
__device__ float g_U[16 * NCH * NCH];              // [xi][ic][oc]
__device__ float g_M[16 * NTP * NCH];              // [xi][tile][oc]
__device__ float g_feat[FSZ * FSZ * NCH];          // [s][oc]
__device__ float4 g_boxes[NKEYS];
__device__ unsigned g_hi[NKEYS];
__device__ unsigned g_hist[NBUCK];
__device__ unsigned g_bcnt[NBUCK];
__device__ unsigned g_bstart[NBUCK + 1];
__device__ unsigned long long g_skey[NKEYS];
__device__ int    g_C;
__device__ float4 g_sboxes[PRE_NMS];
__device__ unsigned g_mask[PRE_NMS * NWORDS];

// ---------------------------------------------------------------------------
// Input transform: V = B^T d B.  One thread per (ic, tile).
// ---------------------------------------------------------------------------
__global__ void prep_x(const float* __restrict__ in) {
    int idx = blockIdx.x * blockDim.x + threadIdx.x;
    if (idx >= NCH * NTP) return;
    int ic = idx / NTP, tile = idx - ic * NTP;
    if (tile >= NTIL) return;
    int ty = tile / 25, tx = tile - ty * 25;

    const float* src = in + ((size_t)(7 * NCH + ic)) * 2500;
    float d[4][4];
#pragma unroll
    for (int i = 0; i < 4; ++i) {
        int py = 2 * ty + i - 1;
#pragma unroll
        for (int j = 0; j < 4; ++j) {
            int px = 2 * tx + j - 1;
            d[i][j] = (py >= 0 && py < 50 && px >= 0 && px < 50)
                      ? src[py * 50 + px] : 0.0f;
        }
    }
    float t[4][4];
#pragma unroll
    for (int j = 0; j < 4; ++j) {
        t[0][j] = d[0][j] - d[2][j];
        t[1][j] = d[1][j] + d[2][j];
        t[2][j] = d[2][j] - d[1][j];
        t[3][j] = d[1][j] - d[3][j];
    }
#pragma unroll
    for (int i = 0; i < 4; ++i) {
        float v0 = t[i][0] - t[i][2];
        float v1 = t[i][1] + t[i][2];
        float v2 = t[i][2] - t[i][1];
        float v3 = t[i][1] - t[i][3];
        g_V[((size_t)(i * 4 + 0) * NCH + ic) * NTP + tile] = v0;
        g_V[((size_t)(i * 4 + 1) * NCH + ic) * NTP + tile] = v1;
        g_V[((size_t)(i * 4 + 2) * NCH + ic) * NTP + tile] = v2;
        g_V[((size_t)(i * 4 + 3) * NCH + ic) * NTP + tile] = v3;
    }
}

// ---------------------------------------------------------------------------
// Weight transform: U = G g G^T. One thread per (ic, oc); also zeroes hists.
// ---------------------------------------------------------------------------
__global__ void prep_w(const float* __restrict__ w) {
    int idx = blockIdx.x * blockDim.x + threadIdx.x;
    if (idx < NBUCK) { g_hist[idx] = 0u; g_bcnt[idx] = 0u; }
    if (idx >= NCH * NCH) return;
    int oc = idx & 511, ic = idx >> 9;

    const float* gp = w + ((size_t)oc * NCH + ic) * 9;
    float g[3][3];
#pragma unroll
    for (int i = 0; i < 3; ++i)
#pragma unroll
        for (int j = 0; j < 3; ++j) g[i][j] = gp[i * 3 + j];

    float T[4][3];
#pragma unroll
    for (int j = 0; j < 3; ++j) {
        T[0][j] = g[0][j];
        T[1][j] = 0.5f * (g[0][j] + g[1][j] + g[2][j]);
        T[2][j] = 0.5f * (g[0][j] - g[1][j] + g[2][j]);
        T[3][j] = g[2][j];
    }
#pragma unroll
    for (int i = 0; i < 4; ++i) {
        float u0 = T[i][0];
        float u1 = 0.5f * (T[i][0] + T[i][1] + T[i][2]);
        float u2 = 0.5f * (T[i][0] - T[i][1] + T[i][2]);
        float u3 = T[i][2];
        g_U[((size_t)(i * 4 + 0) * NCH + ic) * NCH + oc] = u0;
        g_U[((size_t)(i * 4 + 1) * NCH + ic) * NCH + oc] = u1;
        g_U[((size_t)(i * 4 + 2) * NCH + ic) * NCH + oc] = u2;
        g_U[((size_t)(i * 4 + 3) * NCH + ic) * NCH + oc] = u3;
    }
}

// ---------------------------------------------------------------------------
// 16 batched GEMMs: M[xi][tile][oc] = sum_ic U[xi][ic][oc] * V[xi][ic][tile].
// grid=(8 tile-chunks, 8 oc-chunks, 16 xi), 256 thr, 64oc x 80tile per CTA.
// ---------------------------------------------------------------------------
__global__ void __launch_bounds__(256) wgemm_kernel() {
    __shared__ float As[32 * 64];     // [k][oc]
    __shared__ float Bs[32 * 80];     // [k][tile]

    const int tid = threadIdx.x;
    const int to = tid & 15, tw = tid >> 4;
    const int xi = blockIdx.z;
    const int ocb = blockIdx.y * 64;
    const int tb  = blockIdx.x * 80;
    const float* U = g_U + (size_t)xi * NCH * NCH;
    const float* V = g_V + (size_t)xi * NCH * NTP;

    float acc[4][5];
#pragma unroll
    for (int r = 0; r < 4; ++r)
#pragma unroll
        for (int j = 0; j < 5; ++j) acc[r][j] = 0.0f;

    for (int k0 = 0; k0 < NCH; k0 += 32) {
#pragma unroll
        for (int it = 0; it < 2; ++it) {
            int idx = tid + it * 256;
            int row = idx >> 4, q = idx & 15;
            reinterpret_cast<float4*>(As)[idx] =
                *reinterpret_cast<const float4*>(&U[(size_t)(k0 + row) * NCH + ocb + q * 4]);
        }
#pragma unroll
        for (int it = 0; it < 3; ++it) {
            int idx = tid + it * 256;
            if (idx < 640) {
                int row = idx / 20, q = idx - row * 20;
                reinterpret_cast<float4*>(Bs)[idx] =
                    *reinterpret_cast<const float4*>(&V[(size_t)(k0 + row) * NTP + tb + q * 4]);
            }
        }
        __syncthreads();

#pragma unroll 8
        for (int k = 0; k < 32; ++k) {
            float4 a = reinterpret_cast<const float4*>(As)[k * 16 + to];
            const float* bp = &Bs[k * 80 + tw * 5];
            float b0 = bp[0], b1 = bp[1], b2 = bp[2], b3 = bp[3], b4 = bp[4];
            acc[0][0] += a.x * b0; acc[0][1] += a.x * b1; acc[0][2] += a.x * b2;
            acc[0][3] += a.x * b3; acc[0][4] += a.x * b4;
            acc[1][0] += a.y * b0; acc[1][1] += a.y * b1; acc[1][2] += a.y * b2;
            acc[1][3] += a.y * b3; acc[1][4] += a.y * b4;
            acc[2][0] += a.z * b0; acc[2][1] += a.z * b1; acc[2][2] += a.z * b2;
            acc[2][3] += a.z * b3; acc[2][4] += a.z * b4;
            acc[3][0] += a.w * b0; acc[3][1] += a.w * b1; acc[3][2] += a.w * b2;
            acc[3][3] += a.w * b3; acc[3][4] += a.w * b4;
        }
        __syncthreads();
    }

#pragma unroll
    for (int j = 0; j < 5; ++j) {
        float4 v = make_float4(acc[0][j], acc[1][j], acc[2][j], acc[3][j]);
        *reinterpret_cast<float4*>(
            &g_M[((size_t)xi * NTP + tb + tw * 5 + j) * NCH + ocb + to * 4]) = v;
    }
}

// ---------------------------------------------------------------------------
// Output transform: Y = A^T M A, + bias + leaky relu -> g_feat[s][oc].
// One thread per (tile, oc); oc fastest for coalescing.
// ---------------------------------------------------------------------------
__global__ void outtr_kernel(const float* __restrict__ bias) {
    int idx = blockIdx.x * blockDim.x + threadIdx.x;
    if (idx >= NTIL * NCH) return;
    int oc = idx & 511, tile = idx >> 9;
    int ty = tile / 25, tx = tile - ty * 25;

    float m[16];
#pragma unroll
    for (int xi = 0; xi < 16; ++xi)
        m[xi] = g_M[((size_t)xi * NTP + tile) * NCH + oc];

    float t0[4], t1[4];
#pragma unroll
    for (int j = 0; j < 4; ++j) {
        t0[j] = m[j] + m[4 + j] + m[8 + j];
        t1[j] = m[4 + j] - m[8 + j] - m[12 + j];
    }
    float y[2][2];
    y[0][0] = t0[0] + t0[1] + t0[2];
    y[0][1] = t0[1] - t0[2] - t0[3];
    y[1][0] = t1[0] + t1[1] + t1[2];
    y[1][1] = t1[1] - t1[2] - t1[3];

    float bv = bias[oc];
#pragma unroll
    for (int r = 0; r < 2; ++r)
#pragma unroll
        for (int c = 0; c < 2; ++c) {
            float v = y[r][c] + bv;
            v = (v >= 0.0f) ? v : 0.01f * v;
            int s = (2 * ty + r) * FSZ + (2 * tx + c);
            g_feat[(size_t)s * NCH + oc] = v;
        }
}

// ---------------------------------------------------------------------------
// Head (unchanged, proven ~34us).
// ---------------------------------------------------------------------------
#define HB 16
#define WPAD 516
__global__ void __launch_bounds__(512) head_kernel(const float* __restrict__ rw,
                                                   const float* __restrict__ rb,
                                                   const float* __restrict__ cw,
                                                   const float* __restrict__ cb) {
    extern __shared__ float sh[];
    float* Wsp = sh;
    float* ft  = sh + 54 * WPAD;
    __shared__ float bb[54];
    __shared__ float par[2 * HB * 54];
    __shared__ float vals[HB * 54];

    const int tid = threadIdx.x;
    const int s0 = blockIdx.x * HB;

    for (int e = tid; e < 54 * NCH; e += 512) {
        int o = e >> 9, k = e & 511;
        Wsp[o * WPAD + k] = (o < 36) ? rw[o * NCH + k] : cw[(o - 36) * NCH + k];
    }
    if (tid < 54) bb[tid] = (tid < 36) ? rb[tid] : cb[tid - 36];
    for (int e = tid; e < HB * (NCH / 4); e += 512) {
        int sl = e >> 7, k4 = e & 127;
        int s = s0 + sl;
        float4 v = make_float4(0.f, 0.f, 0.f, 0.f);
        if (s < FSZ * FSZ) v = reinterpret_cast<const float4*>(g_feat + (size_t)s * NCH)[k4];
        reinterpret_cast<float4*>(ft + sl * NCH)[k4] = v;
    }
    __syncthreads();

    const int o  = tid & 63;
    const int r  = tid >> 6;
    const int kh = r >> 2;
    const int sg = r & 3;
    if (o < 54) {
        const float4* w4 = reinterpret_cast<const float4*>(Wsp + o * WPAD) + kh * 64;
        const float4* f0 = reinterpret_cast<const float4*>(ft + (sg * 4 + 0) * NCH) + kh * 64;
        const float4* f1 = reinterpret_cast<const float4*>(ft + (sg * 4 + 1) * NCH) + kh * 64;
        const float4* f2 = reinterpret_cast<const float4*>(ft + (sg * 4 + 2) * NCH) + kh * 64;
        const float4* f3 = reinterpret_cast<const float4*>(ft + (sg * 4 + 3) * NCH) + kh * 64;
        float a0 = 0.f, a1 = 0.f, a2 = 0.f, a3 = 0.f;
#pragma unroll 4
        for (int c = 0; c < 64; ++c) {
            float4 w = w4[c];
            float4 f = f0[c];
            a0 += w.x * f.x; a0 += w.y * f.y; a0 += w.z * f.z; a0 += w.w * f.w;
            f = f1[c];
            a1 += w.x * f.x; a1 += w.y * f.y; a1 += w.z * f.z; a1 += w.w * f.w;
            f = f2[c];
            a2 += w.x * f.x; a2 += w.y * f.y; a2 += w.z * f.z; a2 += w.w * f.w;
            f = f3[c];
            a3 += w.x * f.x; a3 += w.y * f.y; a3 += w.z * f.z; a3 += w.w * f.w;
        }
        par[(kh * HB + sg * 4 + 0) * 54 + o] = a0;
        par[(kh * HB + sg * 4 + 1) * 54 + o] = a1;
        par[(kh * HB + sg * 4 + 2) * 54 + o] = a2;
        par[(kh * HB + sg * 4 + 3) * 54 + o] = a3;
    }
    __syncthreads();

    for (int e = tid; e < HB * 54; e += 512) {
        int oo = e % 54;
        vals[e] = (par[e] + par[HB * 54 + e]) + bb[oo];
    }
    __syncthreads();

    if (tid < HB * 9) {
        int sl = tid / 9, a = tid - sl * 9;
        int s = s0 + sl;
        if (s < FSZ * FSZ) {
            const float* v = &vals[sl * 54];
            float pr0 = v[a * 4 + 0], pr1 = v[a * 4 + 1];
            float pr2 = v[a * 4 + 2], pr3 = v[a * 4 + 3];
            float l0 = v[36 + a * 2], l1 = v[36 + a * 2 + 1];
            float m = fmaxf(l0, l1);
            float e0 = expf(l0 - m), e1 = expf(l1 - m);
            float score = e1 / (e0 + e1);

            int hh = s / FSZ, ww = s - hh * FSZ;
            float cx = (float)(16 * hh + 8);
            float cy = (float)(16 * ww + 8);
            int rr = a / 3, q = a - rr * 3;
            float basev = (q == 0) ? 128.0f : (q == 1 ? 256.0f : 512.0f);
            float sq_r  = (rr == 0) ? sqrtf(0.5f) : (rr == 1 ? 1.0f : sqrtf(2.0f));
            float sq_ir = (rr == 0) ? sqrtf(2.0f) : (rr == 1 ? 1.0f : sqrtf(0.5f));
            float hsv = basev * sq_r;
            float wsv = basev * sq_ir;
            float ax1 = cx - wsv * 0.5f;
            float ay1 = cy - hsv * 0.5f;

            float t1 = pr0 + ax1;
            float t2 = pr1 + ay1;
            float rx1 = fminf(fmaxf(t1, 0.0f), 799.0f);
            float ry1 = fminf(fmaxf(t2, 0.0f), 799.0f);
            float rx2 = fminf(fmaxf((t1 + pr2) + wsv, 0.0f), 799.0f);
            float ry2 = fminf(fmaxf((t2 + pr3) + hsv, 0.0f), 799.0f);

            float wv = pr2 + wsv, hv = pr3 + hsv;
            bool valid = (wv >= 16.0f) && (hv >= 16.0f);
            float sm = valid ? score : -INFINITY;

            unsigned u = __float_as_uint(sm);
            unsigned vm = (u & 0x80000000u) ? ~u : (u | 0x80000000u);
            unsigned hi = ~vm;
            int gi = s * 9 + a;
            g_hi[gi] = hi;
            atomicAdd(&g_hist[hi >> 16], 1u);
            g_boxes[gi] = make_float4(rx1, ry1, rx2, ry2);
        }
    }
}

// ---------------------------------------------------------------------------
__global__ void __launch_bounds__(1024) prefix_kernel() {
    const int tid = threadIdx.x;
    const int base = tid * 64;
    unsigned sum = 0;
    for (int k = 0; k < 64; ++k) sum += g_hist[base + k];

    unsigned lane = tid & 31, w = tid >> 5;
    unsigned inc = sum;
#pragma unroll
    for (int d = 1; d < 32; d <<= 1) {
        unsigned n = __shfl_up_sync(0xFFFFFFFFu, inc, d);
        if (lane >= d) inc += n;
    }
    __shared__ unsigned wsum[32];
    if (lane == 31) wsum[w] = inc;
    __syncthreads();
    if (w == 0) {
        unsigned x = wsum[lane];
#pragma unroll
        for (int d = 1; d < 32; d <<= 1) {
            unsigned n = __shfl_up_sync(0xFFFFFFFFu, x, d);
            if (lane >= d) x += n;
        }
        wsum[lane] = x;
    }
    __syncthreads();
    unsigned run = inc - sum + (w ? wsum[w - 1] : 0u);
    for (int k = 0; k < 64; ++k) {
        unsigned hcount = g_hist[base + k];
        g_bstart[base + k] = run;
        unsigned nx = run + hcount;
        if (run < PRE_NMS && nx >= PRE_NMS) g_C = (int)nx;
        run = nx;
    }
    if (tid == 1023) g_bstart[NBUCK] = run;
}

__global__ void __launch_bounds__(256) scatter_kernel() {
    int i = blockIdx.x * 256 + threadIdx.x;
    if (i >= NKEYS) return;
    unsigned hi = g_hi[i];
    unsigned b = hi >> 16;
    unsigned st = g_bstart[b];
    if (st < PRE_NMS) {
        unsigned pos = st + atomicAdd(&g_bcnt[b], 1u);
        g_skey[pos] = ((unsigned long long)hi << 15) | (unsigned)i;
    }
}

__global__ void __launch_bounds__(256) localrank_kernel() {
    int p = blockIdx.x * 256 + threadIdx.x;
    if (p >= g_C) return;
    unsigned long long key = g_skey[p];
    unsigned hi = (unsigned)(key >> 15);
    unsigned b = hi >> 16;
    int s = (int)g_bstart[b], e = (int)g_bstart[b + 1];
    int r = s;
    for (int q = s; q < e; ++q) r += (g_skey[q] < key) ? 1 : 0;
    if (r < PRE_NMS) g_sboxes[r] = g_boxes[key & 0x7FFFu];
}

// ---------------------------------------------------------------------------
__global__ void __launch_bounds__(32) mask_kernel() {
    const int bi = blockIdx.y, bj = blockIdx.x;
    if (bj < bi) return;
    const int t = threadIdx.x;
    const int i = bi * 32 + t;

    __shared__ float4 bx[32];
    __shared__ float ar[32];
    const int j0 = bj * 32;
    if (j0 + t < PRE_NMS) {
        float4 b = g_sboxes[j0 + t];
        bx[t] = b;
        ar[t] = ((b.z - b.x) + 1.0f) * ((b.w - b.y) + 1.0f);
    }
    __syncwarp();
    if (i >= PRE_NMS) return;

    float4 bi4 = g_sboxes[i];
    float areai = ((bi4.z - bi4.x) + 1.0f) * ((bi4.w - bi4.y) + 1.0f);
    unsigned word = 0;
    int jmax = min(32, PRE_NMS - j0);
    for (int jj = 0; jj < jmax; ++jj) {
        int jg = j0 + jj;
        if (jg <= i) continue;
        float4 bj4 = bx[jj];
        float xx1 = fmaxf(bi4.x, bj4.x);
        float yy1 = fmaxf(bi4.y, bj4.y);
        float xx2 = fminf(bi4.z, bj4.z);
        float yy2 = fmaxf(bi4.w, bj4.w);              // reference bug
        float w = fmaxf(0.0f, (xx2 - xx1) + 1.0f);
        float h = fmaxf(0.0f, (yy2 - yy1) + 1.0f);
        float inter = w * h;
        float ov = inter / ((areai + ar[jj]) - inter);
        if (ov > 0.7f) word |= (1u << jj);
    }
    g_mask[i * NWORDS + bj] = word;
}

// ---------------------------------------------------------------------------
__global__ void __launch_bounds__(256) scan_kernel(float* __restrict__ out) {
    __shared__ unsigned keep[NWORDS];
    __shared__ unsigned sdiag[32];
    __shared__ unsigned curAlive;
    __shared__ int pref[NWORDS + 1];
    const int tid = threadIdx.x;
    if (tid < NWORDS) keep[tid] = (tid == NWORDS - 1) ? 0x0000FFFFu : 0xFFFFFFFFu;
    __syncthreads();

    for (int c = 0; c < NWORDS; ++c) {
        if (tid < 32) {
            int i = c * 32 + tid;
            sdiag[tid] = (i < PRE_NMS) ? g_mask[i * NWORDS + c] : 0u;
            __syncwarp();
            if (tid == 0) {
                unsigned alive = keep[c];
                unsigned rem = alive;
                while (rem) {
                    int b = __ffs(rem) - 1;
                    rem &= rem - 1u;
                    alive &= ~sdiag[b];
                    rem &= alive;
                }
                keep[c] = alive;
                curAlive = alive;
            }
        }
        __syncthreads();
        unsigned alive = curAlive;
        if (alive) {
            for (int w2 = c + 1 + tid; w2 < NWORDS; w2 += 256) {
                unsigned nm = 0;
                unsigned a = alive;
                while (a) {
                    int b = __ffs(a) - 1;
                    a &= a - 1u;
                    nm |= g_mask[(c * 32 + b) * NWORDS + w2];
                }
                keep[w2] &= ~nm;
            }
        }
        __syncthreads();
    }

    if (tid == 0) {
        int run = 0;
        pref[0] = 0;
        for (int w = 0; w < NWORDS; ++w) { run += __popc(keep[w]); pref[w + 1] = run; }
    }
    __syncthreads();
    const int K = pref[NWORDS];

    for (int i = tid; i < PRE_NMS; i += 256) {
        int w = i >> 5, b = i & 31;
        unsigned kwv = keep[w];
        int kp = pref[w] + __popc(kwv & ((1u << b) - 1u));
        int pos = ((kwv >> b) & 1u) ? kp : (K + (i - kp));
        if (pos < POST_NMS) {
            float4 bb = g_sboxes[i];
            out[pos * 4 + 0] = bb.x;
            out[pos * 4 + 1] = bb.y;
            out[pos * 4 + 2] = (bb.z - bb.x) + 1.0f;
            out[pos * 4 + 3] = (bb.w - bb.y) + 1.0f;
        }
    }
}

// ---------------------------------------------------------------------------
extern "C" void kernel_launch(void* const* d_in, const int* in_sizes, int n_in,
                              void* d_out, int out_size) {
    const float* in_features = (const float*)d_in[0];
    const float* conv_w      = (const float*)d_in[1];
    const float* conv_b      = (const float*)d_in[2];
    const float* reg_w       = (const float*)d_in[3];
    const float* reg_b       = (const float*)d_in[4];
    const float* cls_w       = (const float*)d_in[5];
    const float* cls_b       = (const float*)d_in[6];
    float* out = (float*)d_out;

    const int head_smem = (54 * WPAD + HB * NCH) * (int)sizeof(float);
    cudaFuncSetAttribute(head_kernel, cudaFuncAttributeMaxDynamicSharedMemorySize, head_smem);

    prep_x<<<(NCH * NTP + 255) / 256, 256>>>(in_features);
    prep_w<<<(NCH * NCH + 255) / 256, 256>>>(conv_w);
    wgemm_kernel<<<dim3(8, 8, 16), 256>>>();
    outtr_kernel<<<(NTIL * NCH + 255) / 256, 256>>>(conv_b);
    head_kernel<<<(FSZ * FSZ + HB - 1) / HB, 512, head_smem>>>(reg_w, reg_b, cls_w, cls_b);
    prefix_kernel<<<1, 1024>>>();
    scatter_kernel<<<(NKEYS + 255) / 256, 256>>>();
    localrank_kernel<<<(NKEYS + 255) / 256, 256>>>();
    mask_kernel<<<dim3(NWORDS, NWORDS), 32>>>();
    scan_kernel<<<1, 256>>>(out);
}